// round 10
// baseline (speedup 1.0000x reference)
#include <cuda_runtime.h>
#include <cuda_fp16.h>
#include <cuda_bf16.h>
#include <cstdint>

#define D_DIM   128
#define K_DIM   512

#define DECAY_F 0.99f
#define ONE_M_DECAY 0.01f
#define EPS_F   1e-5f
#define COMMIT  0.25f
#define MARGIN  1.25f

#define ZP 68    // zh row stride (u32 half2 units) — conflict-free fragments
#define EP 68    // eh row stride
#define DP 260   // dots row stride in u32 (512 half + 16B pad -> row offset 4 banks)

// -------- device scratch (static: no allocation) --------
__device__ float g_counts[K_DIM];
__device__ float g_dw[K_DIM * D_DIM];
__device__ float g_enorm[K_DIM];
__device__ float g_loss_part[64];
__device__ float g_cs[K_DIM];

// D += A(16x16 f16, row) * B(16x8 f16, col), fp32 accum  [base-PTX, sm_80+]
__device__ __forceinline__ void mma_f16(float* d, const uint32_t* a, const uint32_t* b) {
    asm volatile(
        "mma.sync.aligned.m16n8k16.row.col.f32.f16.f16.f32 "
        "{%0,%1,%2,%3}, {%4,%5,%6,%7}, {%8,%9}, {%0,%1,%2,%3};"
        : "+f"(d[0]), "+f"(d[1]), "+f"(d[2]), "+f"(d[3])
        : "r"(a[0]), "r"(a[1]), "r"(a[2]), "r"(a[3]), "r"(b[0]), "r"(b[1]));
}

// ============================================================
// Kernel 1: zero accumulators + ||e_k||^2
// ============================================================
__global__ void __launch_bounds__(256) init_kernel(const float* __restrict__ emb) {
    int tid = blockIdx.x * blockDim.x + threadIdx.x;
    for (int i = tid; i < K_DIM * D_DIM; i += 16384) g_dw[i] = 0.0f;
    if (tid < K_DIM) g_counts[tid] = 0.0f;
    if (tid < 64)    g_loss_part[tid] = 0.0f;

    int w = tid >> 5, lane = tid & 31;
    float4 v = *reinterpret_cast<const float4*>(&emb[w * D_DIM + lane * 4]);
    float s = v.x * v.x + v.y * v.y + v.z * v.z + v.w * v.w;
    #pragma unroll
    for (int off = 16; off > 0; off >>= 1) s += __shfl_xor_sync(0xFFFFFFFFu, s, off);
    if (lane == 0) g_enorm[w] = s;
}

// ============================================================
// Kernel 2 (FUSED): fp16 hi*hi SCREEN (mma.sync) -> fp16 dot table in smem
// -> per-row exact fp32 RESCORE of candidates within MARGIN -> scatter.
// CTA: 128 z-rows x 512 codes, 256 threads = 8 warps as 4(m) x 2(n).
// ============================================================
__global__ void __launch_bounds__(256, 1)
argmin_kernel(const float* __restrict__ z, const float* __restrict__ emb,
              float* __restrict__ idxf_out, float* __restrict__ zq_out) {
    extern __shared__ uint32_t sm[];
    uint32_t* zh   = sm;                 // [128][68] half2 (z hi)
    uint32_t* eh   = zh + 128 * ZP;      // [64][68]  half2 (e hi)
    uint32_t* dots = eh + 64 * EP;       // [128][260] half2 screened dots
    __shared__ float en[K_DIM];
    __shared__ float s_l[8];

    const int tid  = threadIdx.x;
    const int warp = tid >> 5;
    const int lane = tid & 31;
    const int g    = lane >> 2;      // groupID (0..7)
    const int tig  = lane & 3;       // threadID_in_group (0..3)
    const int wm   = warp >> 1;      // 0..3
    const int wn   = warp & 1;       // 0..1
    const int m0   = blockIdx.x * 128;

    #pragma unroll
    for (int i = 0; i < 2; i++) en[tid + i * 256] = g_enorm[tid + i * 256];

    // ---- stage z tile as fp16-hi half2 (coalesced float2 loads) ----
    for (int idx = tid; idx < 128 * 64; idx += 256) {
        int r = idx >> 6, c2 = idx & 63;
        float2 v = *reinterpret_cast<const float2*>(z + (size_t)(m0 + r) * D_DIM + c2 * 2);
        half2 h = __float22half2_rn(v);
        zh[r * ZP + c2] = *reinterpret_cast<uint32_t*>(&h);
    }

    const int rbase = wm * 32 + g;

    // ================= SCREEN =================
    for (int ch = 0; ch < 8; ch++) {
        // prefetch e-chunk into registers before the sync
        float2 pre[16];
        {
            const float* ebase = emb + (size_t)(ch * 64) * D_DIM;
            #pragma unroll
            for (int i = 0; i < 16; i++) {
                int idx = tid + i * 256;
                int n = idx >> 6, c2 = idx & 63;
                pre[i] = *reinterpret_cast<const float2*>(ebase + n * D_DIM + c2 * 2);
            }
        }
        __syncthreads();   // previous chunk's MMAs done reading eh
        #pragma unroll
        for (int i = 0; i < 16; i++) {
            int idx = tid + i * 256;
            int n = idx >> 6, c2 = idx & 63;
            half2 h = __float22half2_rn(pre[i]);
            eh[n * EP + c2] = *reinterpret_cast<uint32_t*>(&h);
        }
        __syncthreads();

        float acc[2][4][4];
        #pragma unroll
        for (int mf = 0; mf < 2; mf++)
            #pragma unroll
            for (int nf = 0; nf < 4; nf++)
                #pragma unroll
                for (int c = 0; c < 4; c++) acc[mf][nf][c] = 0.0f;

        #pragma unroll
        for (int ks = 0; ks < 8; ks++) {
            const int k2 = ks * 8;
            uint32_t ah[2][4];
            #pragma unroll
            for (int mf = 0; mf < 2; mf++) {
                const int r = (rbase + mf * 16) * ZP + k2 + tig;
                ah[mf][0] = zh[r];
                ah[mf][1] = zh[r + 8 * ZP];
                ah[mf][2] = zh[r + 4];
                ah[mf][3] = zh[r + 8 * ZP + 4];
            }
            uint32_t bh[4][2];
            #pragma unroll
            for (int nf = 0; nf < 4; nf++) {
                const int nb = (wn * 32 + nf * 8 + g) * EP + k2 + tig;
                bh[nf][0] = eh[nb];
                bh[nf][1] = eh[nb + 4];
            }
            #pragma unroll
            for (int mf = 0; mf < 2; mf++)
                #pragma unroll
                for (int nf = 0; nf < 4; nf++) mma_f16(acc[mf][nf], ah[mf], bh[nf]);
        }

        // store screened dots as half2 (cols 2tig, 2tig+1)
        #pragma unroll
        for (int mf = 0; mf < 2; mf++) {
            #pragma unroll
            for (int nf = 0; nf < 4; nf++) {
                const int colu = ch * 32 + wn * 16 + nf * 4 + tig;
                half2 p0 = __floats2half2_rn(acc[mf][nf][0], acc[mf][nf][1]);
                half2 p1 = __floats2half2_rn(acc[mf][nf][2], acc[mf][nf][3]);
                dots[(rbase + mf * 16) * DP + colu]     = *reinterpret_cast<uint32_t*>(&p0);
                dots[(rbase + mf * 16 + 8) * DP + colu] = *reinterpret_cast<uint32_t*>(&p1);
            }
        }
    }
    __syncthreads();

    // ================= RESCORE + SCATTER (warp per row, 16 rows/warp) =======
    float lacc = 0.0f;
    for (int it = 0; it < 16; it++) {
        const int r   = warp * 16 + it;
        const int row = m0 + r;

        // z row (fp32, coalesced) — issued early, used in rescore
        float4 zf = *reinterpret_cast<const float4*>(&z[(size_t)row * D_DIM + lane * 4]);

        // pass 1: screened row min
        float mn = 3.4e38f;
        #pragma unroll
        for (int b = 0; b < 512; b += 64) {
            uint32_t u = dots[r * DP + b / 2 + lane];
            float2 d = __half22float2(*reinterpret_cast<half2*>(&u));
            float2 e2 = *reinterpret_cast<const float2*>(&en[b + 2 * lane]);
            float s0 = e2.x - 2.0f * d.x;
            float s1 = e2.y - 2.0f * d.y;
            mn = fminf(mn, fminf(s0, s1));
        }
        #pragma unroll
        for (int off = 16; off > 0; off >>= 1)
            mn = fminf(mn, __shfl_xor_sync(0xFFFFFFFFu, mn, off));
        const float thr = mn + MARGIN;

        // pass 2: candidates within margin -> exact fp32 rescore (streaming)
        float bestv = 3.4e38f;
        int   besti = 0x7FFFFFFF;
        #pragma unroll
        for (int b = 0; b < 512; b += 64) {
            uint32_t u = dots[r * DP + b / 2 + lane];
            float2 d = __half22float2(*reinterpret_cast<half2*>(&u));
            float2 e2 = *reinterpret_cast<const float2*>(&en[b + 2 * lane]);
            float s0 = e2.x - 2.0f * d.x;
            float s1 = e2.y - 2.0f * d.y;
            uint32_t mk0 = __ballot_sync(0xFFFFFFFFu, s0 <= thr);
            uint32_t mk1 = __ballot_sync(0xFFFFFFFFu, s1 <= thr);
            #pragma unroll
            for (int half = 0; half < 2; half++) {
                uint32_t mk = half ? mk1 : mk0;
                while (mk) {
                    int i = __ffs(mk) - 1; mk &= mk - 1;
                    int kc = b + 2 * i + half;
                    float4 q = *reinterpret_cast<const float4*>(
                        &emb[(size_t)kc * D_DIM + lane * 4]);
                    float p = zf.x * q.x + zf.y * q.y + zf.z * q.z + zf.w * q.w;
                    #pragma unroll
                    for (int off = 16; off > 0; off >>= 1)
                        p += __shfl_xor_sync(0xFFFFFFFFu, p, off);
                    float s_ex = en[kc] - 2.0f * p;
                    if (s_ex < bestv || (s_ex == bestv && kc < besti)) {
                        bestv = s_ex; besti = kc;
                    }
                }
            }
        }

        if (lane == 0) idxf_out[row] = (float)besti;

        // scatter: zq, loss, dw + counts atomics
        float4 q = *reinterpret_cast<const float4*>(&emb[(size_t)besti * D_DIM + lane * 4]);
        float dx = q.x - zf.x, dy = q.y - zf.y, dz = q.z - zf.z, dw4 = q.w - zf.w;
        float4 st = make_float4(zf.x + dx, zf.y + dy, zf.z + dz, zf.w + dw4);
        *reinterpret_cast<float4*>(&zq_out[(size_t)row * D_DIM + lane * 4]) = st;

        lacc += dx * dx + dy * dy + dz * dz + dw4 * dw4;

        float* dwp = &g_dw[besti * D_DIM + lane * 4];
        atomicAdd(dwp + 0, zf.x);
        atomicAdd(dwp + 1, zf.y);
        atomicAdd(dwp + 2, zf.z);
        atomicAdd(dwp + 3, zf.w);
        if (lane == 0) atomicAdd(&g_counts[besti], 1.0f);
    }

    // loss reduce: warp -> block partial
    #pragma unroll
    for (int off = 16; off > 0; off >>= 1) lacc += __shfl_xor_sync(0xFFFFFFFFu, lacc, off);
    if (lane == 0) s_l[warp] = lacc;
    __syncthreads();
    if (tid == 0) {
        float b = 0.0f;
        #pragma unroll
        for (int w = 0; w < 8; w++) b += s_l[w];
        atomicAdd(&g_loss_part[blockIdx.x & 63], b);
    }
}

// ============================================================
// Kernel 3a: scalar finalize — ecs EMA, n-reduce, cluster size, loss.
// ============================================================
__global__ void __launch_bounds__(512)
finalize_a(const float* __restrict__ ecs, float* __restrict__ o_ecs,
           float* __restrict__ o_loss, int N) {
    const int k = threadIdx.x;
    __shared__ float red[K_DIM];

    float necs = ecs[k] * DECAY_F + ONE_M_DECAY * g_counts[k];
    o_ecs[k] = necs;
    red[k] = necs;
    __syncthreads();
    #pragma unroll
    for (int s = 256; s > 0; s >>= 1) {
        if (k < s) red[k] += red[k + s];
        __syncthreads();
    }
    float n = red[0];
    g_cs[k] = (necs + EPS_F) / (n + (float)K_DIM * EPS_F) * n;

    if (k == 0) {
        float L = 0.0f;
        #pragma unroll
        for (int j = 0; j < 64; j++) L += g_loss_part[j];
        *o_loss = COMMIT * L / ((float)N * (float)D_DIM);
    }
}

// ============================================================
// Kernel 3b: wide finalize — ema_w EMA + new embedding (K*D elems).
// ============================================================
__global__ void __launch_bounds__(256)
finalize_b(const float* __restrict__ emaw, float* __restrict__ o_emaw,
           float* __restrict__ o_emb) {
    int i = blockIdx.x * 256 + threadIdx.x;
    float w = emaw[i] * DECAY_F + ONE_M_DECAY * g_dw[i];
    o_emaw[i] = w;
    o_emb[i]  = w / g_cs[i >> 7];
}

// ============================================================
// launch
// ============================================================
extern "C" void kernel_launch(void* const* d_in, const int* in_sizes, int n_in,
                              void* d_out, int out_size) {
    const float* z    = (const float*)d_in[0];   // [N, 128]
    const float* emb  = (const float*)d_in[1];   // [512, 128]
    const float* ecs  = (const float*)d_in[2];   // [512]
    const float* emaw = (const float*)d_in[3];   // [512, 128]

    const int ND = in_sizes[0];
    const int KD = in_sizes[1];
    const int K  = in_sizes[2];
    const int N  = ND / D_DIM;

    float* out    = (float*)d_out;
    float* o_zq   = out;                 // N*D
    float* o_loss = o_zq + ND;           // 1
    float* o_idx  = o_loss + 1;          // N
    float* o_ecs  = o_idx + N;           // K
    float* o_emaw = o_ecs + K;           // K*D
    float* o_emb  = o_emaw + KD;         // K*D

    // dyn smem: zh 128*68 + eh 64*68 + dots 128*260 (u32) = 185344 B -> 1 CTA/SM
    const int dyn_smem = (128 * ZP + 64 * EP + 128 * DP) * 4;
    cudaFuncSetAttribute(argmin_kernel,
                         cudaFuncAttributeMaxDynamicSharedMemorySize, dyn_smem);

    init_kernel<<<64, 256>>>(emb);
    argmin_kernel<<<N / 128, 256, dyn_smem>>>(z, emb, o_idx, o_zq);
    finalize_a<<<1, 512>>>(ecs, o_ecs, o_loss, N);
    finalize_b<<<KD / 256, 256>>>(emaw, o_emaw, o_emb);
}

// round 11
// speedup vs baseline: 1.0680x; 1.0680x over previous
#include <cuda_runtime.h>
#include <cuda_fp16.h>
#include <cuda_bf16.h>
#include <cstdint>

#define D_DIM   128
#define K_DIM   512

#define DECAY_F 0.99f
#define ONE_M_DECAY 0.01f
#define EPS_F   1e-5f
#define COMMIT  0.25f
#define MARGIN  1.25f

#define ZP 68    // zh row stride (u32 half2 units) — conflict-free fragments
#define EP 68    // eh row stride
#define DP 260   // dots row stride in u32 (512 half + pad)

// -------- device scratch (static: no allocation) --------
__device__ float g_counts[K_DIM];
__device__ float g_dw[K_DIM * D_DIM];
__device__ float g_enorm[K_DIM];
__device__ float g_loss_part[64];
__device__ float g_cs[K_DIM];

// D += A(16x16 f16, row) * B(16x8 f16, col), fp32 accum  [base-PTX, sm_80+]
__device__ __forceinline__ void mma_f16(float* d, const uint32_t* a, const uint32_t* b) {
    asm volatile(
        "mma.sync.aligned.m16n8k16.row.col.f32.f16.f16.f32 "
        "{%0,%1,%2,%3}, {%4,%5,%6,%7}, {%8,%9}, {%0,%1,%2,%3};"
        : "+f"(d[0]), "+f"(d[1]), "+f"(d[2]), "+f"(d[3])
        : "r"(a[0]), "r"(a[1]), "r"(a[2]), "r"(a[3]), "r"(b[0]), "r"(b[1]));
}

// ============================================================
// Kernel 1: zero accumulators + ||e_k||^2
// ============================================================
__global__ void __launch_bounds__(256) init_kernel(const float* __restrict__ emb) {
    int tid = blockIdx.x * blockDim.x + threadIdx.x;
    for (int i = tid; i < K_DIM * D_DIM; i += 16384) g_dw[i] = 0.0f;
    if (tid < K_DIM) g_counts[tid] = 0.0f;
    if (tid < 64)    g_loss_part[tid] = 0.0f;

    int w = tid >> 5, lane = tid & 31;
    float4 v = *reinterpret_cast<const float4*>(&emb[w * D_DIM + lane * 4]);
    float s = v.x * v.x + v.y * v.y + v.z * v.z + v.w * v.w;
    #pragma unroll
    for (int off = 16; off > 0; off >>= 1) s += __shfl_xor_sync(0xFFFFFFFFu, s, off);
    if (lane == 0) g_enorm[w] = s;
}

// ============================================================
// Kernel 2 (FUSED): fp16 hi*hi SCREEN (mma.sync) -> fp16 dot table in smem
// -> per-row exact fp32 RESCORE within MARGIN -> scatter.
// CTA: 64 z-rows x 512 codes, 256 threads = 8 warps as 2(m) x 4(n).
// 99KB smem -> 2 CTAs/SM (4 warps/SMSP: issue-bound, not latency-bound).
// ============================================================
__global__ void __launch_bounds__(256, 2)
argmin_kernel(const float* __restrict__ z, const float* __restrict__ emb,
              float* __restrict__ idxf_out, float* __restrict__ zq_out) {
    extern __shared__ uint32_t sm[];
    uint32_t* zh   = sm;                 // [64][68] half2 (z hi)
    uint32_t* eh   = zh + 64 * ZP;       // [64][68] half2 (e hi)
    uint32_t* dots = eh + 64 * EP;       // [64][260] half2 screened dots
    __shared__ float en[K_DIM];
    __shared__ float s_l[8];

    const int tid  = threadIdx.x;
    const int warp = tid >> 5;
    const int lane = tid & 31;
    const int g    = lane >> 2;      // groupID (0..7)
    const int tig  = lane & 3;       // threadID_in_group (0..3)
    const int wm   = warp >> 2;      // 0..1  (rows wm*32 .. +32)
    const int wn   = warp & 3;       // 0..3  (cols wn*16 within chunk)
    const int m0   = blockIdx.x * 64;

    #pragma unroll
    for (int i = 0; i < 2; i++) en[tid + i * 256] = g_enorm[tid + i * 256];

    // ---- stage z tile as fp16-hi half2 (coalesced float2 loads) ----
    for (int idx = tid; idx < 64 * 64; idx += 256) {
        int r = idx >> 6, c2 = idx & 63;
        float2 v = *reinterpret_cast<const float2*>(z + (size_t)(m0 + r) * D_DIM + c2 * 2);
        half2 h = __float22half2_rn(v);
        zh[r * ZP + c2] = *reinterpret_cast<uint32_t*>(&h);
    }

    const int rbase = wm * 32 + g;

    // ================= SCREEN =================
    for (int ch = 0; ch < 8; ch++) {
        // prefetch e-chunk into registers before the sync
        float2 pre[16];
        {
            const float* ebase = emb + (size_t)(ch * 64) * D_DIM;
            #pragma unroll
            for (int i = 0; i < 16; i++) {
                int idx = tid + i * 256;
                int n = idx >> 6, c2 = idx & 63;
                pre[i] = *reinterpret_cast<const float2*>(ebase + n * D_DIM + c2 * 2);
            }
        }
        __syncthreads();   // previous chunk's MMAs done reading eh
        #pragma unroll
        for (int i = 0; i < 16; i++) {
            int idx = tid + i * 256;
            int n = idx >> 6, c2 = idx & 63;
            half2 h = __float22half2_rn(pre[i]);
            eh[n * EP + c2] = *reinterpret_cast<uint32_t*>(&h);
        }
        __syncthreads();

        float acc[2][2][4];
        #pragma unroll
        for (int mf = 0; mf < 2; mf++)
            #pragma unroll
            for (int nf = 0; nf < 2; nf++)
                #pragma unroll
                for (int c = 0; c < 4; c++) acc[mf][nf][c] = 0.0f;

        #pragma unroll
        for (int ks = 0; ks < 8; ks++) {
            const int k2 = ks * 8;
            uint32_t ah[2][4];
            #pragma unroll
            for (int mf = 0; mf < 2; mf++) {
                const int r = (rbase + mf * 16) * ZP + k2 + tig;
                ah[mf][0] = zh[r];
                ah[mf][1] = zh[r + 8 * ZP];
                ah[mf][2] = zh[r + 4];
                ah[mf][3] = zh[r + 8 * ZP + 4];
            }
            uint32_t bh[2][2];
            #pragma unroll
            for (int nf = 0; nf < 2; nf++) {
                const int nb = (wn * 16 + nf * 8 + g) * EP + k2 + tig;
                bh[nf][0] = eh[nb];
                bh[nf][1] = eh[nb + 4];
            }
            #pragma unroll
            for (int mf = 0; mf < 2; mf++)
                #pragma unroll
                for (int nf = 0; nf < 2; nf++) mma_f16(acc[mf][nf], ah[mf], bh[nf]);
        }

        // store screened dots as half2 (cols 2tig, 2tig+1 of the nf-subtile)
        #pragma unroll
        for (int mf = 0; mf < 2; mf++) {
            #pragma unroll
            for (int nf = 0; nf < 2; nf++) {
                const int colu = ch * 32 + wn * 8 + nf * 4 + tig;
                half2 p0 = __floats2half2_rn(acc[mf][nf][0], acc[mf][nf][1]);
                half2 p1 = __floats2half2_rn(acc[mf][nf][2], acc[mf][nf][3]);
                dots[(rbase + mf * 16) * DP + colu]     = *reinterpret_cast<uint32_t*>(&p0);
                dots[(rbase + mf * 16 + 8) * DP + colu] = *reinterpret_cast<uint32_t*>(&p1);
            }
        }
    }
    __syncthreads();

    // ================= RESCORE + SCATTER (warp per row, 8 rows/warp) ========
    float lacc = 0.0f;
    for (int it = 0; it < 8; it++) {
        const int r   = warp * 8 + it;
        const int row = m0 + r;

        // z row (fp32, coalesced) — used in rescore + scatter
        float4 zf = *reinterpret_cast<const float4*>(&z[(size_t)row * D_DIM + lane * 4]);

        // pass 1: screened row min
        float mn = 3.4e38f;
        #pragma unroll
        for (int b = 0; b < 512; b += 64) {
            uint32_t u = dots[r * DP + b / 2 + lane];
            float2 d = __half22float2(*reinterpret_cast<half2*>(&u));
            float2 e2 = *reinterpret_cast<const float2*>(&en[b + 2 * lane]);
            float s0 = e2.x - 2.0f * d.x;
            float s1 = e2.y - 2.0f * d.y;
            mn = fminf(mn, fminf(s0, s1));
        }
        #pragma unroll
        for (int off = 16; off > 0; off >>= 1)
            mn = fminf(mn, __shfl_xor_sync(0xFFFFFFFFu, mn, off));
        const float thr = mn + MARGIN;

        // pass 2: candidates within margin -> exact fp32 rescore (streaming)
        float bestv = 3.4e38f;
        int   besti = 0x7FFFFFFF;
        #pragma unroll
        for (int b = 0; b < 512; b += 64) {
            uint32_t u = dots[r * DP + b / 2 + lane];
            float2 d = __half22float2(*reinterpret_cast<half2*>(&u));
            float2 e2 = *reinterpret_cast<const float2*>(&en[b + 2 * lane]);
            float s0 = e2.x - 2.0f * d.x;
            float s1 = e2.y - 2.0f * d.y;
            uint32_t mk0 = __ballot_sync(0xFFFFFFFFu, s0 <= thr);
            uint32_t mk1 = __ballot_sync(0xFFFFFFFFu, s1 <= thr);
            #pragma unroll
            for (int half = 0; half < 2; half++) {
                uint32_t mk = half ? mk1 : mk0;
                while (mk) {
                    int i = __ffs(mk) - 1; mk &= mk - 1;
                    int kc = b + 2 * i + half;
                    float4 q = *reinterpret_cast<const float4*>(
                        &emb[(size_t)kc * D_DIM + lane * 4]);
                    float p = zf.x * q.x + zf.y * q.y + zf.z * q.z + zf.w * q.w;
                    #pragma unroll
                    for (int off = 16; off > 0; off >>= 1)
                        p += __shfl_xor_sync(0xFFFFFFFFu, p, off);
                    float s_ex = en[kc] - 2.0f * p;
                    if (s_ex < bestv || (s_ex == bestv && kc < besti)) {
                        bestv = s_ex; besti = kc;
                    }
                }
            }
        }

        if (lane == 0) idxf_out[row] = (float)besti;

        // scatter: zq, loss, dw + counts atomics
        float4 q = *reinterpret_cast<const float4*>(&emb[(size_t)besti * D_DIM + lane * 4]);
        float dx = q.x - zf.x, dy = q.y - zf.y, dz = q.z - zf.z, dw4 = q.w - zf.w;
        float4 st = make_float4(zf.x + dx, zf.y + dy, zf.z + dz, zf.w + dw4);
        *reinterpret_cast<float4*>(&zq_out[(size_t)row * D_DIM + lane * 4]) = st;

        lacc += dx * dx + dy * dy + dz * dz + dw4 * dw4;

        float* dwp = &g_dw[besti * D_DIM + lane * 4];
        atomicAdd(dwp + 0, zf.x);
        atomicAdd(dwp + 1, zf.y);
        atomicAdd(dwp + 2, zf.z);
        atomicAdd(dwp + 3, zf.w);
        if (lane == 0) atomicAdd(&g_counts[besti], 1.0f);
    }

    // loss reduce: warp -> block partial
    #pragma unroll
    for (int off = 16; off > 0; off >>= 1) lacc += __shfl_xor_sync(0xFFFFFFFFu, lacc, off);
    if (lane == 0) s_l[warp] = lacc;
    __syncthreads();
    if (tid == 0) {
        float b = 0.0f;
        #pragma unroll
        for (int w = 0; w < 8; w++) b += s_l[w];
        atomicAdd(&g_loss_part[blockIdx.x & 63], b);
    }
}

// ============================================================
// Kernel 3a: scalar finalize — ecs EMA, n-reduce, cluster size, loss.
// ============================================================
__global__ void __launch_bounds__(512)
finalize_a(const float* __restrict__ ecs, float* __restrict__ o_ecs,
           float* __restrict__ o_loss, int N) {
    const int k = threadIdx.x;
    __shared__ float red[K_DIM];

    float necs = ecs[k] * DECAY_F + ONE_M_DECAY * g_counts[k];
    o_ecs[k] = necs;
    red[k] = necs;
    __syncthreads();
    #pragma unroll
    for (int s = 256; s > 0; s >>= 1) {
        if (k < s) red[k] += red[k + s];
        __syncthreads();
    }
    float n = red[0];
    g_cs[k] = (necs + EPS_F) / (n + (float)K_DIM * EPS_F) * n;

    if (k == 0) {
        float L = 0.0f;
        #pragma unroll
        for (int j = 0; j < 64; j++) L += g_loss_part[j];
        *o_loss = COMMIT * L / ((float)N * (float)D_DIM);
    }
}

// ============================================================
// Kernel 3b: wide finalize — ema_w EMA + new embedding (K*D elems).
// ============================================================
__global__ void __launch_bounds__(256)
finalize_b(const float* __restrict__ emaw, float* __restrict__ o_emaw,
           float* __restrict__ o_emb) {
    int i = blockIdx.x * 256 + threadIdx.x;
    float w = emaw[i] * DECAY_F + ONE_M_DECAY * g_dw[i];
    o_emaw[i] = w;
    o_emb[i]  = w / g_cs[i >> 7];
}

// ============================================================
// launch
// ============================================================
extern "C" void kernel_launch(void* const* d_in, const int* in_sizes, int n_in,
                              void* d_out, int out_size) {
    const float* z    = (const float*)d_in[0];   // [N, 128]
    const float* emb  = (const float*)d_in[1];   // [512, 128]
    const float* ecs  = (const float*)d_in[2];   // [512]
    const float* emaw = (const float*)d_in[3];   // [512, 128]

    const int ND = in_sizes[0];
    const int KD = in_sizes[1];
    const int K  = in_sizes[2];
    const int N  = ND / D_DIM;

    float* out    = (float*)d_out;
    float* o_zq   = out;                 // N*D
    float* o_loss = o_zq + ND;           // 1
    float* o_idx  = o_loss + 1;          // N
    float* o_ecs  = o_idx + N;           // K
    float* o_emaw = o_ecs + K;           // K*D
    float* o_emb  = o_emaw + KD;         // K*D

    // dyn smem: zh 64*68 + eh 64*68 + dots 64*260 (u32) = 101376 B -> 2 CTAs/SM
    const int dyn_smem = (64 * ZP + 64 * EP + 64 * DP) * 4;
    cudaFuncSetAttribute(argmin_kernel,
                         cudaFuncAttributeMaxDynamicSharedMemorySize, dyn_smem);

    init_kernel<<<64, 256>>>(emb);
    argmin_kernel<<<N / 64, 256, dyn_smem>>>(z, emb, o_idx, o_zq);
    finalize_a<<<1, 512>>>(ecs, o_ecs, o_loss, N);
    finalize_b<<<KD / 256, 256>>>(emaw, o_emaw, o_emb);
}

// round 12
// speedup vs baseline: 1.4371x; 1.3456x over previous
#include <cuda_runtime.h>
#include <cuda_fp16.h>
#include <cuda_bf16.h>
#include <cstdint>

#define D_DIM   128
#define K_DIM   512

#define DECAY_F 0.99f
#define ONE_M_DECAY 0.01f
#define EPS_F   1e-5f
#define COMMIT  0.25f
#define MARGIN  1.25f

#define ZP 68    // zh row stride (u32 half2 units) — conflict-free fragments
#define EP 68    // eh row stride
#define DP 260   // dots row stride in u32 (512 half + pad)

// -------- device scratch (static: no allocation) --------
__device__ float    g_counts[K_DIM];
__device__ float    g_dw[K_DIM * D_DIM];
__device__ float    g_enorm[K_DIM];
__device__ float    g_loss_part[64];
__device__ float    g_cs[K_DIM];
__device__ uint32_t g_emb_h2[K_DIM * 64];   // fp16 embedding, packed half2 (128KB)

// D += A(16x16 f16, row) * B(16x8 f16, col), fp32 accum  [base-PTX, sm_80+]
__device__ __forceinline__ void mma_f16(float* d, const uint32_t* a, const uint32_t* b) {
    asm volatile(
        "mma.sync.aligned.m16n8k16.row.col.f32.f16.f16.f32 "
        "{%0,%1,%2,%3}, {%4,%5,%6,%7}, {%8,%9}, {%0,%1,%2,%3};"
        : "+f"(d[0]), "+f"(d[1]), "+f"(d[2]), "+f"(d[3])
        : "r"(a[0]), "r"(a[1]), "r"(a[2]), "r"(a[3]), "r"(b[0]), "r"(b[1]));
}

// ============================================================
// Kernel 1: zero accumulators + ||e_k||^2 + fp16 embedding copy
// ============================================================
__global__ void __launch_bounds__(256) init_kernel(const float* __restrict__ emb) {
    int tid = blockIdx.x * blockDim.x + threadIdx.x;   // 16384 threads
    for (int i = tid; i < K_DIM * D_DIM; i += 16384) g_dw[i] = 0.0f;
    if (tid < K_DIM) g_counts[tid] = 0.0f;
    if (tid < 64)    g_loss_part[tid] = 0.0f;

    // fp16 copy: 32768 half2 words, 2 per thread
    #pragma unroll
    for (int p = 0; p < 2; p++) {
        int i = tid + p * 16384;
        float2 v = *reinterpret_cast<const float2*>(&emb[i * 2]);
        half2 h = __float22half2_rn(v);
        g_emb_h2[i] = *reinterpret_cast<uint32_t*>(&h);
    }

    int w = tid >> 5, lane = tid & 31;
    float4 v = *reinterpret_cast<const float4*>(&emb[w * D_DIM + lane * 4]);
    float s = v.x * v.x + v.y * v.y + v.z * v.z + v.w * v.w;
    #pragma unroll
    for (int off = 16; off > 0; off >>= 1) s += __shfl_xor_sync(0xFFFFFFFFu, s, off);
    if (lane == 0) g_enorm[w] = s;
}

// ============================================================
// Kernel 2 (FUSED): fp16 hi*hi SCREEN (mma.sync) -> fp16 dot table in smem
// -> per-row exact fp32 RESCORE within MARGIN -> scatter.
// CTA: 64 z-rows x 512 codes, 256 threads = 8 warps as 2(m) x 4(n).
// e-tiles loaded pre-converted (uint4) from g_emb_h2. 99KB smem -> 2 CTAs/SM.
// ============================================================
__global__ void __launch_bounds__(256, 2)
argmin_kernel(const float* __restrict__ z, const float* __restrict__ emb,
              float* __restrict__ idxf_out, float* __restrict__ zq_out) {
    extern __shared__ uint32_t sm[];
    uint32_t* zh   = sm;                 // [64][68] half2 (z hi)
    uint32_t* eh   = zh + 64 * ZP;       // [64][68] half2 (e hi)
    uint32_t* dots = eh + 64 * EP;       // [64][260] half2 screened dots
    __shared__ float en[K_DIM];
    __shared__ float s_l[8];

    const int tid  = threadIdx.x;
    const int warp = tid >> 5;
    const int lane = tid & 31;
    const int g    = lane >> 2;      // groupID (0..7)
    const int tig  = lane & 3;       // threadID_in_group (0..3)
    const int wm   = warp >> 2;      // 0..1  (rows wm*32 .. +32)
    const int wn   = warp & 3;       // 0..3  (cols wn*16 within chunk)
    const int m0   = blockIdx.x * 64;

    #pragma unroll
    for (int i = 0; i < 2; i++) en[tid + i * 256] = g_enorm[tid + i * 256];

    // ---- stage z tile as fp16-hi half2 (coalesced float4 loads) ----
    for (int idx = tid; idx < 64 * 32; idx += 256) {
        int r = idx >> 5, c4 = idx & 31;
        float4 v = *reinterpret_cast<const float4*>(z + (size_t)(m0 + r) * D_DIM + c4 * 4);
        half2 h0 = __floats2half2_rn(v.x, v.y);
        half2 h1 = __floats2half2_rn(v.z, v.w);
        zh[r * ZP + c4 * 2]     = *reinterpret_cast<uint32_t*>(&h0);
        zh[r * ZP + c4 * 2 + 1] = *reinterpret_cast<uint32_t*>(&h1);
    }

    const int rbase = wm * 32 + g;

    // ================= SCREEN =================
    for (int ch = 0; ch < 8; ch++) {
        // prefetch pre-converted e-chunk (uint4) before the sync
        uint4 pre[4];
        {
            const uint4* ebase = reinterpret_cast<const uint4*>(g_emb_h2 + ch * 64 * 64);
            #pragma unroll
            for (int p = 0; p < 4; p++) pre[p] = ebase[tid + p * 256];
        }
        __syncthreads();   // previous chunk's MMAs done reading eh
        #pragma unroll
        for (int p = 0; p < 4; p++) {
            int u = tid + p * 256;          // 1024 uint4 total: 64 rows x 16
            int n = u >> 4, c4 = (u & 15) * 4;
            *reinterpret_cast<uint4*>(&eh[n * EP + c4]) = pre[p];
        }
        __syncthreads();

        float acc[2][2][4];
        #pragma unroll
        for (int mf = 0; mf < 2; mf++)
            #pragma unroll
            for (int nf = 0; nf < 2; nf++)
                #pragma unroll
                for (int c = 0; c < 4; c++) acc[mf][nf][c] = 0.0f;

        #pragma unroll
        for (int ks = 0; ks < 8; ks++) {
            const int k2 = ks * 8;
            uint32_t ah[2][4];
            #pragma unroll
            for (int mf = 0; mf < 2; mf++) {
                const int r = (rbase + mf * 16) * ZP + k2 + tig;
                ah[mf][0] = zh[r];
                ah[mf][1] = zh[r + 8 * ZP];
                ah[mf][2] = zh[r + 4];
                ah[mf][3] = zh[r + 8 * ZP + 4];
            }
            uint32_t bh[2][2];
            #pragma unroll
            for (int nf = 0; nf < 2; nf++) {
                const int nb = (wn * 16 + nf * 8 + g) * EP + k2 + tig;
                bh[nf][0] = eh[nb];
                bh[nf][1] = eh[nb + 4];
            }
            #pragma unroll
            for (int mf = 0; mf < 2; mf++)
                #pragma unroll
                for (int nf = 0; nf < 2; nf++) mma_f16(acc[mf][nf], ah[mf], bh[nf]);
        }

        // store screened dots as half2
        #pragma unroll
        for (int mf = 0; mf < 2; mf++) {
            #pragma unroll
            for (int nf = 0; nf < 2; nf++) {
                const int colu = ch * 32 + wn * 8 + nf * 4 + tig;
                half2 p0 = __floats2half2_rn(acc[mf][nf][0], acc[mf][nf][1]);
                half2 p1 = __floats2half2_rn(acc[mf][nf][2], acc[mf][nf][3]);
                dots[(rbase + mf * 16) * DP + colu]     = *reinterpret_cast<uint32_t*>(&p0);
                dots[(rbase + mf * 16 + 8) * DP + colu] = *reinterpret_cast<uint32_t*>(&p1);
            }
        }
    }
    __syncthreads();

    // ================= RESCORE + SCATTER (warp per row, 8 rows/warp) ========
    float lacc = 0.0f;
    for (int it = 0; it < 8; it++) {
        const int r   = warp * 8 + it;
        const int row = m0 + r;

        float4 zf = *reinterpret_cast<const float4*>(&z[(size_t)row * D_DIM + lane * 4]);

        // pass 1: screened row min
        float mn = 3.4e38f;
        #pragma unroll
        for (int b = 0; b < 512; b += 64) {
            uint32_t u = dots[r * DP + b / 2 + lane];
            float2 d = __half22float2(*reinterpret_cast<half2*>(&u));
            float2 e2 = *reinterpret_cast<const float2*>(&en[b + 2 * lane]);
            float s0 = e2.x - 2.0f * d.x;
            float s1 = e2.y - 2.0f * d.y;
            mn = fminf(mn, fminf(s0, s1));
        }
        #pragma unroll
        for (int off = 16; off > 0; off >>= 1)
            mn = fminf(mn, __shfl_xor_sync(0xFFFFFFFFu, mn, off));
        const float thr = mn + MARGIN;

        // pass 2: candidates within margin -> exact fp32 rescore (streaming)
        float bestv = 3.4e38f;
        int   besti = 0x7FFFFFFF;
        #pragma unroll
        for (int b = 0; b < 512; b += 64) {
            uint32_t u = dots[r * DP + b / 2 + lane];
            float2 d = __half22float2(*reinterpret_cast<half2*>(&u));
            float2 e2 = *reinterpret_cast<const float2*>(&en[b + 2 * lane]);
            float s0 = e2.x - 2.0f * d.x;
            float s1 = e2.y - 2.0f * d.y;
            uint32_t mk0 = __ballot_sync(0xFFFFFFFFu, s0 <= thr);
            uint32_t mk1 = __ballot_sync(0xFFFFFFFFu, s1 <= thr);
            #pragma unroll
            for (int half = 0; half < 2; half++) {
                uint32_t mk = half ? mk1 : mk0;
                while (mk) {
                    int i = __ffs(mk) - 1; mk &= mk - 1;
                    int kc = b + 2 * i + half;
                    float4 q = *reinterpret_cast<const float4*>(
                        &emb[(size_t)kc * D_DIM + lane * 4]);
                    float p = zf.x * q.x + zf.y * q.y + zf.z * q.z + zf.w * q.w;
                    #pragma unroll
                    for (int off = 16; off > 0; off >>= 1)
                        p += __shfl_xor_sync(0xFFFFFFFFu, p, off);
                    float s_ex = en[kc] - 2.0f * p;
                    if (s_ex < bestv || (s_ex == bestv && kc < besti)) {
                        bestv = s_ex; besti = kc;
                    }
                }
            }
        }

        if (lane == 0) idxf_out[row] = (float)besti;

        // scatter: zq, loss, dw (vector red) + counts
        float4 q = *reinterpret_cast<const float4*>(&emb[(size_t)besti * D_DIM + lane * 4]);
        float dx = q.x - zf.x, dy = q.y - zf.y, dz = q.z - zf.z, dw4 = q.w - zf.w;
        float4 st = make_float4(zf.x + dx, zf.y + dy, zf.z + dz, zf.w + dw4);
        *reinterpret_cast<float4*>(&zq_out[(size_t)row * D_DIM + lane * 4]) = st;

        lacc += dx * dx + dy * dy + dz * dz + dw4 * dw4;

        float* dwp = &g_dw[besti * D_DIM + lane * 4];
        asm volatile("red.global.add.v4.f32 [%0], {%1, %2, %3, %4};"
                     :: "l"(dwp), "f"(zf.x), "f"(zf.y), "f"(zf.z), "f"(zf.w)
                     : "memory");
        if (lane == 0) atomicAdd(&g_counts[besti], 1.0f);
    }

    // loss reduce: warp -> block partial
    #pragma unroll
    for (int off = 16; off > 0; off >>= 1) lacc += __shfl_xor_sync(0xFFFFFFFFu, lacc, off);
    if (lane == 0) s_l[warp] = lacc;
    __syncthreads();
    if (tid == 0) {
        float b = 0.0f;
        #pragma unroll
        for (int w = 0; w < 8; w++) b += s_l[w];
        atomicAdd(&g_loss_part[blockIdx.x & 63], b);
    }
}

// ============================================================
// Kernel 3a: scalar finalize — ecs EMA, n-reduce, cluster size, loss.
// ============================================================
__global__ void __launch_bounds__(512)
finalize_a(const float* __restrict__ ecs, float* __restrict__ o_ecs,
           float* __restrict__ o_loss, int N) {
    const int k = threadIdx.x;
    __shared__ float red[K_DIM];

    float necs = ecs[k] * DECAY_F + ONE_M_DECAY * g_counts[k];
    o_ecs[k] = necs;
    red[k] = necs;
    __syncthreads();
    #pragma unroll
    for (int s = 256; s > 0; s >>= 1) {
        if (k < s) red[k] += red[k + s];
        __syncthreads();
    }
    float n = red[0];
    g_cs[k] = (necs + EPS_F) / (n + (float)K_DIM * EPS_F) * n;

    if (k == 0) {
        float L = 0.0f;
        #pragma unroll
        for (int j = 0; j < 64; j++) L += g_loss_part[j];
        *o_loss = COMMIT * L / ((float)N * (float)D_DIM);
    }
}

// ============================================================
// Kernel 3b: wide finalize — ema_w EMA + new embedding (K*D elems).
// ============================================================
__global__ void __launch_bounds__(256)
finalize_b(const float* __restrict__ emaw, float* __restrict__ o_emaw,
           float* __restrict__ o_emb) {
    int i = blockIdx.x * 256 + threadIdx.x;
    float w = emaw[i] * DECAY_F + ONE_M_DECAY * g_dw[i];
    o_emaw[i] = w;
    o_emb[i]  = w / g_cs[i >> 7];
}

// ============================================================
// launch
// ============================================================
extern "C" void kernel_launch(void* const* d_in, const int* in_sizes, int n_in,
                              void* d_out, int out_size) {
    const float* z    = (const float*)d_in[0];   // [N, 128]
    const float* emb  = (const float*)d_in[1];   // [512, 128]
    const float* ecs  = (const float*)d_in[2];   // [512]
    const float* emaw = (const float*)d_in[3];   // [512, 128]

    const int ND = in_sizes[0];
    const int KD = in_sizes[1];
    const int K  = in_sizes[2];
    const int N  = ND / D_DIM;

    float* out    = (float*)d_out;
    float* o_zq   = out;                 // N*D
    float* o_loss = o_zq + ND;           // 1
    float* o_idx  = o_loss + 1;          // N
    float* o_ecs  = o_idx + N;           // K
    float* o_emaw = o_ecs + K;           // K*D
    float* o_emb  = o_emaw + KD;         // K*D

    // dyn smem: zh 64*68 + eh 64*68 + dots 64*260 (u32) = 101376 B -> 2 CTAs/SM
    const int dyn_smem = (64 * ZP + 64 * EP + 64 * DP) * 4;
    cudaFuncSetAttribute(argmin_kernel,
                         cudaFuncAttributeMaxDynamicSharedMemorySize, dyn_smem);

    init_kernel<<<64, 256>>>(emb);
    argmin_kernel<<<N / 64, 256, dyn_smem>>>(z, emb, o_idx, o_zq);
    finalize_a<<<1, 512>>>(ecs, o_ecs, o_loss, N);
    finalize_b<<<KD / 256, 256>>>(emaw, o_emaw, o_emb);
}

// round 13
// speedup vs baseline: 1.6076x; 1.1186x over previous
#include <cuda_runtime.h>
#include <cuda_fp16.h>
#include <cuda_bf16.h>
#include <cstdint>

#define D_DIM   128
#define K_DIM   512

#define DECAY_F 0.99f
#define ONE_M_DECAY 0.01f
#define EPS_F   1e-5f
#define COMMIT  0.25f
#define MARGIN  1.25f

#define ZP 68    // zh row stride (u32 half2 units) — conflict-free fragments
#define EP 68    // eh row stride
#define DP 260   // dots row stride in u32 (512 half + pad; 260 = 4*65 keeps uint4 align)

// -------- device scratch (static: no allocation) --------
__device__ float    g_counts[K_DIM];
__device__ float    g_dw[K_DIM * D_DIM];
__device__ float    g_enorm[K_DIM];
__device__ float    g_loss_part[64];
__device__ float    g_cs[K_DIM];
__device__ uint32_t g_emb_h2[K_DIM * 64];   // fp16 embedding, packed half2 (128KB)

// D += A(16x16 f16, row) * B(16x8 f16, col), fp32 accum  [base-PTX, sm_80+]
__device__ __forceinline__ void mma_f16(float* d, const uint32_t* a, const uint32_t* b) {
    asm volatile(
        "mma.sync.aligned.m16n8k16.row.col.f32.f16.f16.f32 "
        "{%0,%1,%2,%3}, {%4,%5,%6,%7}, {%8,%9}, {%0,%1,%2,%3};"
        : "+f"(d[0]), "+f"(d[1]), "+f"(d[2]), "+f"(d[3])
        : "r"(a[0]), "r"(a[1]), "r"(a[2]), "r"(a[3]), "r"(b[0]), "r"(b[1]));
}

// monotonic float -> uint key (order-preserving); and inverse
__device__ __forceinline__ uint32_t fkey(float f) {
    uint32_t u = __float_as_uint(f);
    return (u & 0x80000000u) ? ~u : (u ^ 0x80000000u);
}
__device__ __forceinline__ float funkey(uint32_t k) {
    uint32_t u = (k & 0x80000000u) ? (k ^ 0x80000000u) : ~k;
    return __uint_as_float(u);
}

// ============================================================
// Kernel 1: zero accumulators + ||e_k||^2 + fp16 embedding copy
// ============================================================
__global__ void __launch_bounds__(256) init_kernel(const float* __restrict__ emb) {
    int tid = blockIdx.x * blockDim.x + threadIdx.x;   // 16384 threads
    for (int i = tid; i < K_DIM * D_DIM; i += 16384) g_dw[i] = 0.0f;
    if (tid < K_DIM) g_counts[tid] = 0.0f;
    if (tid < 64)    g_loss_part[tid] = 0.0f;

    #pragma unroll
    for (int p = 0; p < 2; p++) {
        int i = tid + p * 16384;
        float2 v = *reinterpret_cast<const float2*>(&emb[i * 2]);
        half2 h = __float22half2_rn(v);
        g_emb_h2[i] = *reinterpret_cast<uint32_t*>(&h);
    }

    int w = tid >> 5, lane = tid & 31;
    float4 v = *reinterpret_cast<const float4*>(&emb[w * D_DIM + lane * 4]);
    float s = v.x * v.x + v.y * v.y + v.z * v.z + v.w * v.w;
    #pragma unroll
    for (int off = 16; off > 0; off >>= 1) s += __shfl_xor_sync(0xFFFFFFFFu, s, off);
    if (lane == 0) g_enorm[w] = s;
}

// ============================================================
// Kernel 2 (FUSED): fp16 hi*hi SCREEN -> registerized RESCORE -> scatter.
// CTA: 64 z-rows x 512 codes, 256 threads = 8 warps as 2(m) x 4(n).
// Tail: lane owns codes [8L,8L+8) and [256+8L,256+8L+8); REDUX row-min,
// single-ballot candidate enum, cnt==1 fast path.
// ============================================================
__global__ void __launch_bounds__(256, 2)
argmin_kernel(const float* __restrict__ z, const float* __restrict__ emb,
              float* __restrict__ idxf_out, float* __restrict__ zq_out) {
    extern __shared__ uint32_t sm[];
    uint32_t* zh   = sm;                 // [64][68] half2 (z hi)
    uint32_t* eh   = zh + 64 * ZP;       // [64][68] half2 (e hi)
    uint32_t* dots = eh + 64 * EP;       // [64][260] half2 screened dots
    __shared__ float en[K_DIM];
    __shared__ float s_l[8];

    const int tid  = threadIdx.x;
    const int warp = tid >> 5;
    const int lane = tid & 31;
    const int g    = lane >> 2;
    const int tig  = lane & 3;
    const int wm   = warp >> 2;      // 0..1
    const int wn   = warp & 3;       // 0..3
    const int m0   = blockIdx.x * 64;

    #pragma unroll
    for (int i = 0; i < 2; i++) en[tid + i * 256] = g_enorm[tid + i * 256];

    // ---- stage z tile as fp16-hi half2 (coalesced float4 loads) ----
    for (int idx = tid; idx < 64 * 32; idx += 256) {
        int r = idx >> 5, c4 = idx & 31;
        float4 v = *reinterpret_cast<const float4*>(z + (size_t)(m0 + r) * D_DIM + c4 * 4);
        half2 h0 = __floats2half2_rn(v.x, v.y);
        half2 h1 = __floats2half2_rn(v.z, v.w);
        zh[r * ZP + c4 * 2]     = *reinterpret_cast<uint32_t*>(&h0);
        zh[r * ZP + c4 * 2 + 1] = *reinterpret_cast<uint32_t*>(&h1);
    }

    const int rbase = wm * 32 + g;

    // ================= SCREEN =================
    for (int ch = 0; ch < 8; ch++) {
        uint4 pre[4];
        {
            const uint4* ebase = reinterpret_cast<const uint4*>(g_emb_h2 + ch * 64 * 64);
            #pragma unroll
            for (int p = 0; p < 4; p++) pre[p] = ebase[tid + p * 256];
        }
        __syncthreads();
        #pragma unroll
        for (int p = 0; p < 4; p++) {
            int u = tid + p * 256;
            int n = u >> 4, c4 = (u & 15) * 4;
            *reinterpret_cast<uint4*>(&eh[n * EP + c4]) = pre[p];
        }
        __syncthreads();

        float acc[2][2][4];
        #pragma unroll
        for (int mf = 0; mf < 2; mf++)
            #pragma unroll
            for (int nf = 0; nf < 2; nf++)
                #pragma unroll
                for (int c = 0; c < 4; c++) acc[mf][nf][c] = 0.0f;

        #pragma unroll
        for (int ks = 0; ks < 8; ks++) {
            const int k2 = ks * 8;
            uint32_t ah[2][4];
            #pragma unroll
            for (int mf = 0; mf < 2; mf++) {
                const int r = (rbase + mf * 16) * ZP + k2 + tig;
                ah[mf][0] = zh[r];
                ah[mf][1] = zh[r + 8 * ZP];
                ah[mf][2] = zh[r + 4];
                ah[mf][3] = zh[r + 8 * ZP + 4];
            }
            uint32_t bh[2][2];
            #pragma unroll
            for (int nf = 0; nf < 2; nf++) {
                const int nb = (wn * 16 + nf * 8 + g) * EP + k2 + tig;
                bh[nf][0] = eh[nb];
                bh[nf][1] = eh[nb + 4];
            }
            #pragma unroll
            for (int mf = 0; mf < 2; mf++)
                #pragma unroll
                for (int nf = 0; nf < 2; nf++) mma_f16(acc[mf][nf], ah[mf], bh[nf]);
        }

        #pragma unroll
        for (int mf = 0; mf < 2; mf++) {
            #pragma unroll
            for (int nf = 0; nf < 2; nf++) {
                const int colu = ch * 32 + wn * 8 + nf * 4 + tig;
                half2 p0 = __floats2half2_rn(acc[mf][nf][0], acc[mf][nf][1]);
                half2 p1 = __floats2half2_rn(acc[mf][nf][2], acc[mf][nf][3]);
                dots[(rbase + mf * 16) * DP + colu]     = *reinterpret_cast<uint32_t*>(&p0);
                dots[(rbase + mf * 16 + 8) * DP + colu] = *reinterpret_cast<uint32_t*>(&p1);
            }
        }
    }
    __syncthreads();

    // ================= RESCORE + SCATTER (warp per row, 8 rows/warp) ========
    // lane owns codes A: [8*lane, 8*lane+8) and B: [256+8*lane, 256+8*lane+8)
    float enA[8], enB[8];
    #pragma unroll
    for (int t = 0; t < 2; t++) {
        float4 a = *reinterpret_cast<const float4*>(&en[8 * lane + 4 * t]);
        float4 b = *reinterpret_cast<const float4*>(&en[256 + 8 * lane + 4 * t]);
        enA[4 * t + 0] = a.x; enA[4 * t + 1] = a.y; enA[4 * t + 2] = a.z; enA[4 * t + 3] = a.w;
        enB[4 * t + 0] = b.x; enB[4 * t + 1] = b.y; enB[4 * t + 2] = b.z; enB[4 * t + 3] = b.w;
    }

    float lacc = 0.0f;
    #pragma unroll 2
    for (int it = 0; it < 8; it++) {
        const int r   = warp * 8 + it;
        const int row = m0 + r;

        float4 zf = *reinterpret_cast<const float4*>(&z[(size_t)row * D_DIM + lane * 4]);

        // load this lane's 16 screened dots (2 x LDS.128), compute scores
        const uint4* drow = reinterpret_cast<const uint4*>(&dots[r * DP]);
        uint4 qa = drow[lane];
        uint4 qb = drow[32 + lane];
        float sA[8], sB[8];
        {
            const uint32_t* ua = reinterpret_cast<const uint32_t*>(&qa);
            const uint32_t* ub = reinterpret_cast<const uint32_t*>(&qb);
            #pragma unroll
            for (int t = 0; t < 4; t++) {
                float2 da = __half22float2(*reinterpret_cast<const half2*>(&ua[t]));
                float2 db = __half22float2(*reinterpret_cast<const half2*>(&ub[t]));
                sA[2 * t]     = enA[2 * t]     - 2.0f * da.x;
                sA[2 * t + 1] = enA[2 * t + 1] - 2.0f * da.y;
                sB[2 * t]     = enB[2 * t]     - 2.0f * db.x;
                sB[2 * t + 1] = enB[2 * t + 1] - 2.0f * db.y;
            }
        }
        // lane-local min, then warp REDUX min
        float lm = sA[0];
        #pragma unroll
        for (int j = 1; j < 8; j++) lm = fminf(lm, sA[j]);
        #pragma unroll
        for (int j = 0; j < 8; j++) lm = fminf(lm, sB[j]);
        float mn  = funkey(__reduce_min_sync(0xFFFFFFFFu, fkey(lm)));
        float thr = mn + MARGIN;

        // candidate mask (bit j: code 8L+j; bit 8+j: code 256+8L+j)
        uint32_t m16 = 0;
        #pragma unroll
        for (int j = 0; j < 8; j++) {
            m16 |= (sA[j] <= thr) ? (1u << j) : 0u;
            m16 |= (sB[j] <= thr) ? (1u << (8 + j)) : 0u;
        }
        uint32_t ball = __ballot_sync(0xFFFFFFFFu, m16 != 0);
        uint32_t cnt  = __reduce_add_sync(0xFFFFFFFFu, (uint32_t)__popc(m16));

        int besti;
        if (cnt == 1) {
            // single candidate -> it IS the exact argmin (margin >= 2*err bound)
            int src = __ffs(ball) - 1;
            uint32_t m = __shfl_sync(0xFFFFFFFFu, m16, src);
            int b = __ffs(m) - 1;
            besti = (b < 8) ? (8 * src + b) : (256 + 8 * src + (b - 8));
        } else {
            float bestv = 3.4e38f;
            besti = 0x7FFFFFFF;
            uint32_t bl = ball;
            while (bl) {
                int src = __ffs(bl) - 1; bl &= bl - 1;
                uint32_t m = __shfl_sync(0xFFFFFFFFu, m16, src);
                while (m) {
                    int b = __ffs(m) - 1; m &= m - 1;
                    int kc = (b < 8) ? (8 * src + b) : (256 + 8 * src + (b - 8));
                    float4 q = *reinterpret_cast<const float4*>(
                        &emb[(size_t)kc * D_DIM + lane * 4]);
                    float p = zf.x * q.x + zf.y * q.y + zf.z * q.z + zf.w * q.w;
                    #pragma unroll
                    for (int off = 16; off > 0; off >>= 1)
                        p += __shfl_xor_sync(0xFFFFFFFFu, p, off);
                    float s_ex = en[kc] - 2.0f * p;
                    if (s_ex < bestv || (s_ex == bestv && kc < besti)) {
                        bestv = s_ex; besti = kc;
                    }
                }
            }
        }

        if (lane == 0) idxf_out[row] = (float)besti;

        // scatter: zq, loss, dw (vector red) + counts
        float4 q = *reinterpret_cast<const float4*>(&emb[(size_t)besti * D_DIM + lane * 4]);
        float dx = q.x - zf.x, dy = q.y - zf.y, dz = q.z - zf.z, dw4 = q.w - zf.w;
        float4 st = make_float4(zf.x + dx, zf.y + dy, zf.z + dz, zf.w + dw4);
        *reinterpret_cast<float4*>(&zq_out[(size_t)row * D_DIM + lane * 4]) = st;

        lacc += dx * dx + dy * dy + dz * dz + dw4 * dw4;

        float* dwp = &g_dw[besti * D_DIM + lane * 4];
        asm volatile("red.global.add.v4.f32 [%0], {%1, %2, %3, %4};"
                     :: "l"(dwp), "f"(zf.x), "f"(zf.y), "f"(zf.z), "f"(zf.w)
                     : "memory");
        if (lane == 0) atomicAdd(&g_counts[besti], 1.0f);
    }

    // loss reduce: warp -> block partial
    #pragma unroll
    for (int off = 16; off > 0; off >>= 1) lacc += __shfl_xor_sync(0xFFFFFFFFu, lacc, off);
    if (lane == 0) s_l[warp] = lacc;
    __syncthreads();
    if (tid == 0) {
        float b = 0.0f;
        #pragma unroll
        for (int w = 0; w < 8; w++) b += s_l[w];
        atomicAdd(&g_loss_part[blockIdx.x & 63], b);
    }
}

// ============================================================
// Kernel 3a: scalar finalize — ecs EMA, n-reduce, cluster size, loss.
// ============================================================
__global__ void __launch_bounds__(512)
finalize_a(const float* __restrict__ ecs, float* __restrict__ o_ecs,
           float* __restrict__ o_loss, int N) {
    const int k = threadIdx.x;
    __shared__ float red[K_DIM];

    float necs = ecs[k] * DECAY_F + ONE_M_DECAY * g_counts[k];
    o_ecs[k] = necs;
    red[k] = necs;
    __syncthreads();
    #pragma unroll
    for (int s = 256; s > 0; s >>= 1) {
        if (k < s) red[k] += red[k + s];
        __syncthreads();
    }
    float n = red[0];
    g_cs[k] = (necs + EPS_F) / (n + (float)K_DIM * EPS_F) * n;

    if (k == 0) {
        float L = 0.0f;
        #pragma unroll
        for (int j = 0; j < 64; j++) L += g_loss_part[j];
        *o_loss = COMMIT * L / ((float)N * (float)D_DIM);
    }
}

// ============================================================
// Kernel 3b: wide finalize — ema_w EMA + new embedding (K*D elems).
// ============================================================
__global__ void __launch_bounds__(256)
finalize_b(const float* __restrict__ emaw, float* __restrict__ o_emaw,
           float* __restrict__ o_emb) {
    int i = blockIdx.x * 256 + threadIdx.x;
    float w = emaw[i] * DECAY_F + ONE_M_DECAY * g_dw[i];
    o_emaw[i] = w;
    o_emb[i]  = w / g_cs[i >> 7];
}

// ============================================================
// launch
// ============================================================
extern "C" void kernel_launch(void* const* d_in, const int* in_sizes, int n_in,
                              void* d_out, int out_size) {
    const float* z    = (const float*)d_in[0];   // [N, 128]
    const float* emb  = (const float*)d_in[1];   // [512, 128]
    const float* ecs  = (const float*)d_in[2];   // [512]
    const float* emaw = (const float*)d_in[3];   // [512, 128]

    const int ND = in_sizes[0];
    const int KD = in_sizes[1];
    const int K  = in_sizes[2];
    const int N  = ND / D_DIM;

    float* out    = (float*)d_out;
    float* o_zq   = out;                 // N*D
    float* o_loss = o_zq + ND;           // 1
    float* o_idx  = o_loss + 1;          // N
    float* o_ecs  = o_idx + N;           // K
    float* o_emaw = o_ecs + K;           // K*D
    float* o_emb  = o_emaw + KD;         // K*D

    // dyn smem: zh 64*68 + eh 64*68 + dots 64*260 (u32) = 101376 B -> 2 CTAs/SM
    const int dyn_smem = (64 * ZP + 64 * EP + 64 * DP) * 4;
    cudaFuncSetAttribute(argmin_kernel,
                         cudaFuncAttributeMaxDynamicSharedMemorySize, dyn_smem);

    init_kernel<<<64, 256>>>(emb);
    argmin_kernel<<<N / 64, 256, dyn_smem>>>(z, emb, o_idx, o_zq);
    finalize_a<<<1, 512>>>(ecs, o_ecs, o_loss, N);
    finalize_b<<<KD / 256, 256>>>(emaw, o_emaw, o_emb);
}

// round 14
// speedup vs baseline: 1.8165x; 1.1300x over previous
#include <cuda_runtime.h>
#include <cuda_fp16.h>
#include <cuda_bf16.h>
#include <cstdint>

#define D_DIM   128
#define K_DIM   512

#define DECAY_F 0.99f
#define ONE_M_DECAY 0.01f
#define EPS_F   1e-5f
#define COMMIT  0.25f
#define MARGIN  1.25f

#define EP 68        // e row stride (u32) — conflict-free fragments
#define DP 260       // dots row stride (u32); 260 mod 32 = 4 -> conflict-free epilogue STS
#define EBUF (64 * EP)

// -------- device scratch (static: no allocation) --------
__device__ float    g_counts[K_DIM];
__device__ float    g_dw[K_DIM * D_DIM];
__device__ float    g_enorm[K_DIM];
__device__ float    g_loss_part[64];
__device__ float    g_cs[K_DIM];
__device__ uint32_t g_emb_h2[K_DIM * 64];   // fp16 embedding, packed half2 (128KB)

// D += A(16x16 f16, row) * B(16x8 f16, col), fp32 accum  [base-PTX, sm_80+]
__device__ __forceinline__ void mma_f16(float* d, const uint32_t* a, const uint32_t* b) {
    asm volatile(
        "mma.sync.aligned.m16n8k16.row.col.f32.f16.f16.f32 "
        "{%0,%1,%2,%3}, {%4,%5,%6,%7}, {%8,%9}, {%0,%1,%2,%3};"
        : "+f"(d[0]), "+f"(d[1]), "+f"(d[2]), "+f"(d[3])
        : "r"(a[0]), "r"(a[1]), "r"(a[2]), "r"(a[3]), "r"(b[0]), "r"(b[1]));
}

// monotonic float -> uint key (order-preserving); and inverse
__device__ __forceinline__ uint32_t fkey(float f) {
    uint32_t u = __float_as_uint(f);
    return (u & 0x80000000u) ? ~u : (u ^ 0x80000000u);
}
__device__ __forceinline__ float funkey(uint32_t k) {
    uint32_t u = (k & 0x80000000u) ? (k ^ 0x80000000u) : ~k;
    return __uint_as_float(u);
}

// ============================================================
// Kernel 1: zero accumulators + ||e_k||^2 + fp16 embedding copy
// ============================================================
__global__ void __launch_bounds__(256) init_kernel(const float* __restrict__ emb) {
    int tid = blockIdx.x * blockDim.x + threadIdx.x;   // 16384 threads
    for (int i = tid; i < K_DIM * D_DIM; i += 16384) g_dw[i] = 0.0f;
    if (tid < K_DIM) g_counts[tid] = 0.0f;
    if (tid < 64)    g_loss_part[tid] = 0.0f;

    #pragma unroll
    for (int p = 0; p < 2; p++) {
        int i = tid + p * 16384;
        float2 v = *reinterpret_cast<const float2*>(&emb[i * 2]);
        half2 h = __float22half2_rn(v);
        g_emb_h2[i] = *reinterpret_cast<uint32_t*>(&h);
    }

    int w = tid >> 5, lane = tid & 31;
    float4 v = *reinterpret_cast<const float4*>(&emb[w * D_DIM + lane * 4]);
    float s = v.x * v.x + v.y * v.y + v.z * v.z + v.w * v.w;
    #pragma unroll
    for (int off = 16; off > 0; off >>= 1) s += __shfl_xor_sync(0xFFFFFFFFu, s, off);
    if (lane == 0) g_enorm[w] = s;
}

// ============================================================
// Kernel 2 (FUSED): fp16 hi*hi SCREEN -> registerized RESCORE -> scatter.
// A fragments registerized once (64 regs); e tiles double-buffered.
// CTA: 64 z-rows x 512 codes, 256 threads = 8 warps as 2(m) x 4(n).
// ============================================================
__global__ void __launch_bounds__(256, 2)
argmin_kernel(const float* __restrict__ z, const float* __restrict__ emb,
              float* __restrict__ idxf_out, float* __restrict__ zq_out) {
    extern __shared__ uint32_t sm[];
    uint32_t* ebuf = sm;                 // [2][64*68] half2 e tiles (buf0 stages z first)
    uint32_t* dots = ebuf + 2 * EBUF;    // [64][260] half2 screened dots
    __shared__ float en[K_DIM];
    __shared__ float s_l[8];

    const int tid  = threadIdx.x;
    const int warp = tid >> 5;
    const int lane = tid & 31;
    const int g    = lane >> 2;
    const int tig  = lane & 3;
    const int wm   = warp >> 2;      // 0..1
    const int wn   = warp & 3;       // 0..3
    const int m0   = blockIdx.x * 64;

    #pragma unroll
    for (int i = 0; i < 2; i++) en[tid + i * 256] = g_enorm[tid + i * 256];

    // ---- stage z tile (f32 -> half2) into ebuf[0] ----
    for (int idx = tid; idx < 64 * 32; idx += 256) {
        int r = idx >> 5, c4 = idx & 31;
        float4 v = *reinterpret_cast<const float4*>(z + (size_t)(m0 + r) * D_DIM + c4 * 4);
        half2 h0 = __floats2half2_rn(v.x, v.y);
        half2 h1 = __floats2half2_rn(v.z, v.w);
        ebuf[r * EP + c4 * 2]     = *reinterpret_cast<uint32_t*>(&h0);
        ebuf[r * EP + c4 * 2 + 1] = *reinterpret_cast<uint32_t*>(&h1);
    }

    // prefetch e chunk 0 (hides under z extraction)
    const uint4* e4 = reinterpret_cast<const uint4*>(g_emb_h2);
    uint4 pre[4];
    #pragma unroll
    for (int p = 0; p < 4; p++) pre[p] = e4[tid + p * 256];

    __syncthreads();

    // ---- extract A fragments for ALL 8 k-steps into registers (64 u32) ----
    uint32_t areg[2][8][4];
    #pragma unroll
    for (int mf = 0; mf < 2; mf++) {
        const int row = wm * 32 + g + mf * 16;
        #pragma unroll
        for (int ks = 0; ks < 8; ks++) {
            const int k2 = ks * 8;
            areg[mf][ks][0] = ebuf[row * EP + k2 + tig];
            areg[mf][ks][1] = ebuf[(row + 8) * EP + k2 + tig];
            areg[mf][ks][2] = ebuf[row * EP + k2 + 4 + tig];
            areg[mf][ks][3] = ebuf[(row + 8) * EP + k2 + 4 + tig];
        }
    }
    __syncthreads();   // all extractions done before overwriting ebuf[0]

    // store chunk 0 into buf0
    #pragma unroll
    for (int p = 0; p < 4; p++) {
        int u = tid + p * 256;
        int n = u >> 4, c4 = (u & 15) * 4;
        *reinterpret_cast<uint4*>(&ebuf[n * EP + c4]) = pre[p];
    }
    __syncthreads();

    // ================= SCREEN (double-buffered) =================
    for (int ch = 0; ch < 8; ch++) {
        uint32_t* cur = ebuf + (ch & 1) * EBUF;

        // prefetch chunk ch+1 early (LDG latency hides under MMA block)
        if (ch < 7) {
            #pragma unroll
            for (int p = 0; p < 4; p++) pre[p] = e4[(ch + 1) * 1024 + tid + p * 256];
        }

        float acc[2][2][4];
        #pragma unroll
        for (int mf = 0; mf < 2; mf++)
            #pragma unroll
            for (int nf = 0; nf < 2; nf++)
                #pragma unroll
                for (int c = 0; c < 4; c++) acc[mf][nf][c] = 0.0f;

        #pragma unroll
        for (int ks = 0; ks < 8; ks++) {
            const int k2 = ks * 8;
            uint32_t bh[2][2];
            #pragma unroll
            for (int nf = 0; nf < 2; nf++) {
                const int nb = (wn * 16 + nf * 8 + g) * EP + k2 + tig;
                bh[nf][0] = cur[nb];
                bh[nf][1] = cur[nb + 4];
            }
            #pragma unroll
            for (int mf = 0; mf < 2; mf++)
                #pragma unroll
                for (int nf = 0; nf < 2; nf++) mma_f16(acc[mf][nf], areg[mf][ks], bh[nf]);
        }

        // dots epilogue (conflict-free: DP mod 32 == 4)
        #pragma unroll
        for (int mf = 0; mf < 2; mf++) {
            #pragma unroll
            for (int nf = 0; nf < 2; nf++) {
                const int colu = ch * 32 + wn * 8 + nf * 4 + tig;
                const int rowb = wm * 32 + g + mf * 16;
                half2 p0 = __floats2half2_rn(acc[mf][nf][0], acc[mf][nf][1]);
                half2 p1 = __floats2half2_rn(acc[mf][nf][2], acc[mf][nf][3]);
                dots[rowb * DP + colu]       = *reinterpret_cast<uint32_t*>(&p0);
                dots[(rowb + 8) * DP + colu] = *reinterpret_cast<uint32_t*>(&p1);
            }
        }

        if (ch < 7) {
            __syncthreads();   // all warps done reading buf[(ch+1)&1] (chunk ch-1)
            uint32_t* nxt = ebuf + ((ch + 1) & 1) * EBUF;
            #pragma unroll
            for (int p = 0; p < 4; p++) {
                int u = tid + p * 256;
                int n = u >> 4, c4 = (u & 15) * 4;
                *reinterpret_cast<uint4*>(&nxt[n * EP + c4]) = pre[p];
            }
            __syncthreads();
        }
    }
    __syncthreads();

    // ================= RESCORE + SCATTER (warp per row, 8 rows/warp) ========
    float enA[8], enB[8];
    #pragma unroll
    for (int t = 0; t < 2; t++) {
        float4 a = *reinterpret_cast<const float4*>(&en[8 * lane + 4 * t]);
        float4 b = *reinterpret_cast<const float4*>(&en[256 + 8 * lane + 4 * t]);
        enA[4 * t + 0] = a.x; enA[4 * t + 1] = a.y; enA[4 * t + 2] = a.z; enA[4 * t + 3] = a.w;
        enB[4 * t + 0] = b.x; enB[4 * t + 1] = b.y; enB[4 * t + 2] = b.z; enB[4 * t + 3] = b.w;
    }

    float lacc = 0.0f;
    #pragma unroll 2
    for (int it = 0; it < 8; it++) {
        const int r   = warp * 8 + it;
        const int row = m0 + r;

        float4 zf = *reinterpret_cast<const float4*>(&z[(size_t)row * D_DIM + lane * 4]);

        const uint4* drow = reinterpret_cast<const uint4*>(&dots[r * DP]);
        uint4 qa = drow[lane];
        uint4 qb = drow[32 + lane];
        float sA[8], sB[8];
        {
            const uint32_t* ua = reinterpret_cast<const uint32_t*>(&qa);
            const uint32_t* ub = reinterpret_cast<const uint32_t*>(&qb);
            #pragma unroll
            for (int t = 0; t < 4; t++) {
                float2 da = __half22float2(*reinterpret_cast<const half2*>(&ua[t]));
                float2 db = __half22float2(*reinterpret_cast<const half2*>(&ub[t]));
                sA[2 * t]     = enA[2 * t]     - 2.0f * da.x;
                sA[2 * t + 1] = enA[2 * t + 1] - 2.0f * da.y;
                sB[2 * t]     = enB[2 * t]     - 2.0f * db.x;
                sB[2 * t + 1] = enB[2 * t + 1] - 2.0f * db.y;
            }
        }
        float lm = sA[0];
        #pragma unroll
        for (int j = 1; j < 8; j++) lm = fminf(lm, sA[j]);
        #pragma unroll
        for (int j = 0; j < 8; j++) lm = fminf(lm, sB[j]);
        float mn  = funkey(__reduce_min_sync(0xFFFFFFFFu, fkey(lm)));
        float thr = mn + MARGIN;

        uint32_t m16 = 0;
        #pragma unroll
        for (int j = 0; j < 8; j++) {
            m16 |= (sA[j] <= thr) ? (1u << j) : 0u;
            m16 |= (sB[j] <= thr) ? (1u << (8 + j)) : 0u;
        }
        uint32_t ball = __ballot_sync(0xFFFFFFFFu, m16 != 0);
        uint32_t cnt  = __reduce_add_sync(0xFFFFFFFFu, (uint32_t)__popc(m16));

        int besti;
        if (cnt == 1) {
            int src = __ffs(ball) - 1;
            uint32_t m = __shfl_sync(0xFFFFFFFFu, m16, src);
            int b = __ffs(m) - 1;
            besti = (b < 8) ? (8 * src + b) : (256 + 8 * src + (b - 8));
        } else {
            float bestv = 3.4e38f;
            besti = 0x7FFFFFFF;
            uint32_t bl = ball;
            while (bl) {
                int src = __ffs(bl) - 1; bl &= bl - 1;
                uint32_t m = __shfl_sync(0xFFFFFFFFu, m16, src);
                while (m) {
                    int b = __ffs(m) - 1; m &= m - 1;
                    int kc = (b < 8) ? (8 * src + b) : (256 + 8 * src + (b - 8));
                    float4 q = *reinterpret_cast<const float4*>(
                        &emb[(size_t)kc * D_DIM + lane * 4]);
                    float p = zf.x * q.x + zf.y * q.y + zf.z * q.z + zf.w * q.w;
                    #pragma unroll
                    for (int off = 16; off > 0; off >>= 1)
                        p += __shfl_xor_sync(0xFFFFFFFFu, p, off);
                    float s_ex = en[kc] - 2.0f * p;
                    if (s_ex < bestv || (s_ex == bestv && kc < besti)) {
                        bestv = s_ex; besti = kc;
                    }
                }
            }
        }

        if (lane == 0) idxf_out[row] = (float)besti;

        float4 q = *reinterpret_cast<const float4*>(&emb[(size_t)besti * D_DIM + lane * 4]);
        float dx = q.x - zf.x, dy = q.y - zf.y, dz = q.z - zf.z, dw4 = q.w - zf.w;
        float4 st = make_float4(zf.x + dx, zf.y + dy, zf.z + dz, zf.w + dw4);
        *reinterpret_cast<float4*>(&zq_out[(size_t)row * D_DIM + lane * 4]) = st;

        lacc += dx * dx + dy * dy + dz * dz + dw4 * dw4;

        float* dwp = &g_dw[besti * D_DIM + lane * 4];
        asm volatile("red.global.add.v4.f32 [%0], {%1, %2, %3, %4};"
                     :: "l"(dwp), "f"(zf.x), "f"(zf.y), "f"(zf.z), "f"(zf.w)
                     : "memory");
        if (lane == 0) atomicAdd(&g_counts[besti], 1.0f);
    }

    #pragma unroll
    for (int off = 16; off > 0; off >>= 1) lacc += __shfl_xor_sync(0xFFFFFFFFu, lacc, off);
    if (lane == 0) s_l[warp] = lacc;
    __syncthreads();
    if (tid == 0) {
        float b = 0.0f;
        #pragma unroll
        for (int w = 0; w < 8; w++) b += s_l[w];
        atomicAdd(&g_loss_part[blockIdx.x & 63], b);
    }
}

// ============================================================
// Kernel 3a: scalar finalize — ecs EMA, n-reduce, cluster size, loss.
// ============================================================
__global__ void __launch_bounds__(512)
finalize_a(const float* __restrict__ ecs, float* __restrict__ o_ecs,
           float* __restrict__ o_loss, int N) {
    const int k = threadIdx.x;
    __shared__ float red[K_DIM];

    float necs = ecs[k] * DECAY_F + ONE_M_DECAY * g_counts[k];
    o_ecs[k] = necs;
    red[k] = necs;
    __syncthreads();
    #pragma unroll
    for (int s = 256; s > 0; s >>= 1) {
        if (k < s) red[k] += red[k + s];
        __syncthreads();
    }
    float n = red[0];
    g_cs[k] = (necs + EPS_F) / (n + (float)K_DIM * EPS_F) * n;

    if (k == 0) {
        float L = 0.0f;
        #pragma unroll
        for (int j = 0; j < 64; j++) L += g_loss_part[j];
        *o_loss = COMMIT * L / ((float)N * (float)D_DIM);
    }
}

// ============================================================
// Kernel 3b: wide finalize — ema_w EMA + new embedding (K*D elems).
// ============================================================
__global__ void __launch_bounds__(256)
finalize_b(const float* __restrict__ emaw, float* __restrict__ o_emaw,
           float* __restrict__ o_emb) {
    int i = blockIdx.x * 256 + threadIdx.x;
    float w = emaw[i] * DECAY_F + ONE_M_DECAY * g_dw[i];
    o_emaw[i] = w;
    o_emb[i]  = w / g_cs[i >> 7];
}

// ============================================================
// launch
// ============================================================
extern "C" void kernel_launch(void* const* d_in, const int* in_sizes, int n_in,
                              void* d_out, int out_size) {
    const float* z    = (const float*)d_in[0];   // [N, 128]
    const float* emb  = (const float*)d_in[1];   // [512, 128]
    const float* ecs  = (const float*)d_in[2];   // [512]
    const float* emaw = (const float*)d_in[3];   // [512, 128]

    const int ND = in_sizes[0];
    const int KD = in_sizes[1];
    const int K  = in_sizes[2];
    const int N  = ND / D_DIM;

    float* out    = (float*)d_out;
    float* o_zq   = out;                 // N*D
    float* o_loss = o_zq + ND;           // 1
    float* o_idx  = o_loss + 1;          // N
    float* o_ecs  = o_idx + N;           // K
    float* o_emaw = o_ecs + K;           // K*D
    float* o_emb  = o_emaw + KD;         // K*D

    // dyn smem: ebuf 2*64*68 + dots 64*260 (u32) = 101376 B -> 2 CTAs/SM
    const int dyn_smem = (2 * EBUF + 64 * DP) * 4;
    cudaFuncSetAttribute(argmin_kernel,
                         cudaFuncAttributeMaxDynamicSharedMemorySize, dyn_smem);

    init_kernel<<<64, 256>>>(emb);
    argmin_kernel<<<N / 64, 256, dyn_smem>>>(z, emb, o_idx, o_zq);
    finalize_a<<<1, 512>>>(ecs, o_ecs, o_loss, N);
    finalize_b<<<KD / 256, 256>>>(emaw, o_emaw, o_emb);
}

// round 15
// speedup vs baseline: 1.8179x; 1.0008x over previous
#include <cuda_runtime.h>
#include <cuda_fp16.h>
#include <cuda_bf16.h>
#include <cstdint>

#define D_DIM   128
#define K_DIM   512

#define DECAY_F 0.99f
#define ONE_M_DECAY 0.01f
#define EPS_F   1e-5f
#define COMMIT  0.25f
#define MARGIN  1.25f

#define EP 68        // e row stride (u32) — conflict-free fragments
#define DP 260       // dots row stride (u32); 260 mod 32 = 4 -> conflict-free epilogue STS
#define EBUF (64 * EP)

// -------- device scratch (static: no allocation) --------
__device__ float    g_counts[K_DIM];
__device__ float    g_dw[K_DIM * D_DIM];
__device__ float    g_enorm[K_DIM];
__device__ float    g_loss_part[64];
__device__ float    g_cs[K_DIM];
__device__ uint32_t g_emb_h2[K_DIM * 64];   // fp16 embedding, packed half2 (128KB)

// D += A(16x16 f16, row) * B(16x8 f16, col), fp32 accum  [base-PTX, sm_80+]
__device__ __forceinline__ void mma_f16(float* d, const uint32_t* a, const uint32_t* b) {
    asm volatile(
        "mma.sync.aligned.m16n8k16.row.col.f32.f16.f16.f32 "
        "{%0,%1,%2,%3}, {%4,%5,%6,%7}, {%8,%9}, {%0,%1,%2,%3};"
        : "+f"(d[0]), "+f"(d[1]), "+f"(d[2]), "+f"(d[3])
        : "r"(a[0]), "r"(a[1]), "r"(a[2]), "r"(a[3]), "r"(b[0]), "r"(b[1]));
}

// monotonic float -> uint key (order-preserving); and inverse
__device__ __forceinline__ uint32_t fkey(float f) {
    uint32_t u = __float_as_uint(f);
    return (u & 0x80000000u) ? ~u : (u ^ 0x80000000u);
}
__device__ __forceinline__ float funkey(uint32_t k) {
    uint32_t u = (k & 0x80000000u) ? (k ^ 0x80000000u) : ~k;
    return __uint_as_float(u);
}

// ============================================================
// Kernel 1: zero accumulators + ||e_k||^2 + fp16 embedding copy
// ============================================================
__global__ void __launch_bounds__(256) init_kernel(const float* __restrict__ emb) {
    int tid = blockIdx.x * blockDim.x + threadIdx.x;   // 16384 threads
    for (int i = tid; i < K_DIM * D_DIM; i += 16384) g_dw[i] = 0.0f;
    if (tid < K_DIM) g_counts[tid] = 0.0f;
    if (tid < 64)    g_loss_part[tid] = 0.0f;

    #pragma unroll
    for (int p = 0; p < 2; p++) {
        int i = tid + p * 16384;
        float2 v = *reinterpret_cast<const float2*>(&emb[i * 2]);
        half2 h = __float22half2_rn(v);
        g_emb_h2[i] = *reinterpret_cast<uint32_t*>(&h);
    }

    int w = tid >> 5, lane = tid & 31;
    float4 v = *reinterpret_cast<const float4*>(&emb[w * D_DIM + lane * 4]);
    float s = v.x * v.x + v.y * v.y + v.z * v.z + v.w * v.w;
    #pragma unroll
    for (int off = 16; off > 0; off >>= 1) s += __shfl_xor_sync(0xFFFFFFFFu, s, off);
    if (lane == 0) g_enorm[w] = s;
}

// ============================================================
// Kernel 2 (FUSED): fp16 hi*hi SCREEN -> registerized RESCORE -> scatter.
// A fragments registerized once; e tiles double-buffered, ONE sync/chunk.
// Tail software-pipelined (next row's zf + dots prefetched).
// CTA: 64 z-rows x 512 codes, 256 threads = 8 warps as 2(m) x 4(n).
// ============================================================
__global__ void __launch_bounds__(256, 2)
argmin_kernel(const float* __restrict__ z, const float* __restrict__ emb,
              float* __restrict__ idxf_out, float* __restrict__ zq_out) {
    extern __shared__ uint32_t sm[];
    uint32_t* ebuf = sm;                 // [2][64*68] half2 e tiles (buf0 stages z first)
    uint32_t* dots = ebuf + 2 * EBUF;    // [64][260] half2 screened dots
    __shared__ float en[K_DIM];
    __shared__ float s_l[8];

    const int tid  = threadIdx.x;
    const int warp = tid >> 5;
    const int lane = tid & 31;
    const int g    = lane >> 2;
    const int tig  = lane & 3;
    const int wm   = warp >> 2;      // 0..1
    const int wn   = warp & 3;       // 0..3
    const int m0   = blockIdx.x * 64;

    #pragma unroll
    for (int i = 0; i < 2; i++) en[tid + i * 256] = g_enorm[tid + i * 256];

    // ---- stage z tile (f32 -> half2) into ebuf[0] ----
    for (int idx = tid; idx < 64 * 32; idx += 256) {
        int r = idx >> 5, c4 = idx & 31;
        float4 v = *reinterpret_cast<const float4*>(z + (size_t)(m0 + r) * D_DIM + c4 * 4);
        half2 h0 = __floats2half2_rn(v.x, v.y);
        half2 h1 = __floats2half2_rn(v.z, v.w);
        ebuf[r * EP + c4 * 2]     = *reinterpret_cast<uint32_t*>(&h0);
        ebuf[r * EP + c4 * 2 + 1] = *reinterpret_cast<uint32_t*>(&h1);
    }

    // prefetch e chunk 0 (hides under z extraction)
    const uint4* e4 = reinterpret_cast<const uint4*>(g_emb_h2);
    uint4 pre[4];
    #pragma unroll
    for (int p = 0; p < 4; p++) pre[p] = e4[tid + p * 256];

    __syncthreads();

    // ---- extract A fragments for ALL 8 k-steps into registers (64 u32) ----
    uint32_t areg[2][8][4];
    #pragma unroll
    for (int mf = 0; mf < 2; mf++) {
        const int row = wm * 32 + g + mf * 16;
        #pragma unroll
        for (int ks = 0; ks < 8; ks++) {
            const int k2 = ks * 8;
            areg[mf][ks][0] = ebuf[row * EP + k2 + tig];
            areg[mf][ks][1] = ebuf[(row + 8) * EP + k2 + tig];
            areg[mf][ks][2] = ebuf[row * EP + k2 + 4 + tig];
            areg[mf][ks][3] = ebuf[(row + 8) * EP + k2 + 4 + tig];
        }
    }
    __syncthreads();   // all extractions done before overwriting ebuf[0]

    // store chunk 0 into buf0
    #pragma unroll
    for (int p = 0; p < 4; p++) {
        int u = tid + p * 256;
        int n = u >> 4, c4 = (u & 15) * 4;
        *reinterpret_cast<uint4*>(&ebuf[n * EP + c4]) = pre[p];
    }
    __syncthreads();

    // ================= SCREEN (double-buffered, ONE sync per chunk) ========
    // Order per chunk: MMA(cur) -> dots epilogue -> STS(next) -> sync.
    // The sync at end of chunk ch-1 guarantees (a) all warps' MMA(ch-1) done
    // before any STS overwrites that buffer, (b) all STS(ch) done before MMA(ch).
    for (int ch = 0; ch < 8; ch++) {
        uint32_t* cur = ebuf + (ch & 1) * EBUF;

        // prefetch chunk ch+1 early (LDG latency hides under MMA block)
        if (ch < 7) {
            #pragma unroll
            for (int p = 0; p < 4; p++) pre[p] = e4[(ch + 1) * 1024 + tid + p * 256];
        }

        float acc[2][2][4];
        #pragma unroll
        for (int mf = 0; mf < 2; mf++)
            #pragma unroll
            for (int nf = 0; nf < 2; nf++)
                #pragma unroll
                for (int c = 0; c < 4; c++) acc[mf][nf][c] = 0.0f;

        #pragma unroll
        for (int ks = 0; ks < 8; ks++) {
            const int k2 = ks * 8;
            uint32_t bh[2][2];
            #pragma unroll
            for (int nf = 0; nf < 2; nf++) {
                const int nb = (wn * 16 + nf * 8 + g) * EP + k2 + tig;
                bh[nf][0] = cur[nb];
                bh[nf][1] = cur[nb + 4];
            }
            #pragma unroll
            for (int mf = 0; mf < 2; mf++)
                #pragma unroll
                for (int nf = 0; nf < 2; nf++) mma_f16(acc[mf][nf], areg[mf][ks], bh[nf]);
        }

        // dots epilogue (conflict-free: DP mod 32 == 4)
        #pragma unroll
        for (int mf = 0; mf < 2; mf++) {
            #pragma unroll
            for (int nf = 0; nf < 2; nf++) {
                const int colu = ch * 32 + wn * 8 + nf * 4 + tig;
                const int rowb = wm * 32 + g + mf * 16;
                half2 p0 = __floats2half2_rn(acc[mf][nf][0], acc[mf][nf][1]);
                half2 p1 = __floats2half2_rn(acc[mf][nf][2], acc[mf][nf][3]);
                dots[rowb * DP + colu]       = *reinterpret_cast<uint32_t*>(&p0);
                dots[(rowb + 8) * DP + colu] = *reinterpret_cast<uint32_t*>(&p1);
            }
        }

        if (ch < 7) {
            uint32_t* nxt = ebuf + ((ch + 1) & 1) * EBUF;
            #pragma unroll
            for (int p = 0; p < 4; p++) {
                int u = tid + p * 256;
                int n = u >> 4, c4 = (u & 15) * 4;
                *reinterpret_cast<uint4*>(&nxt[n * EP + c4]) = pre[p];
            }
            __syncthreads();
        }
    }
    __syncthreads();   // dots table complete & visible to all warps

    // ================= RESCORE + SCATTER (warp per row, 8 rows/warp) ========
    float enA[8], enB[8];
    #pragma unroll
    for (int t = 0; t < 2; t++) {
        float4 a = *reinterpret_cast<const float4*>(&en[8 * lane + 4 * t]);
        float4 b = *reinterpret_cast<const float4*>(&en[256 + 8 * lane + 4 * t]);
        enA[4 * t + 0] = a.x; enA[4 * t + 1] = a.y; enA[4 * t + 2] = a.z; enA[4 * t + 3] = a.w;
        enB[4 * t + 0] = b.x; enB[4 * t + 1] = b.y; enB[4 * t + 2] = b.z; enB[4 * t + 3] = b.w;
    }

    float lacc = 0.0f;
    const int r0 = warp * 8;

    // software pipeline: preload row r0
    float4 zf = *reinterpret_cast<const float4*>(&z[(size_t)(m0 + r0) * D_DIM + lane * 4]);
    uint4  qa, qb;
    {
        const uint4* d0 = reinterpret_cast<const uint4*>(&dots[r0 * DP]);
        qa = d0[lane]; qb = d0[32 + lane];
    }

    for (int it = 0; it < 8; it++) {
        const int r   = r0 + it;
        const int row = m0 + r;

        const float4 zc = zf;
        const uint4  qac = qa, qbc = qb;
        if (it < 7) {   // issue next row's loads before the serial chain
            zf = *reinterpret_cast<const float4*>(&z[(size_t)(row + 1) * D_DIM + lane * 4]);
            const uint4* dn = reinterpret_cast<const uint4*>(&dots[(r + 1) * DP]);
            qa = dn[lane]; qb = dn[32 + lane];
        }

        float sA[8], sB[8];
        {
            const uint32_t* ua = reinterpret_cast<const uint32_t*>(&qac);
            const uint32_t* ub = reinterpret_cast<const uint32_t*>(&qbc);
            #pragma unroll
            for (int t = 0; t < 4; t++) {
                float2 da = __half22float2(*reinterpret_cast<const half2*>(&ua[t]));
                float2 db = __half22float2(*reinterpret_cast<const half2*>(&ub[t]));
                sA[2 * t]     = enA[2 * t]     - 2.0f * da.x;
                sA[2 * t + 1] = enA[2 * t + 1] - 2.0f * da.y;
                sB[2 * t]     = enB[2 * t]     - 2.0f * db.x;
                sB[2 * t + 1] = enB[2 * t + 1] - 2.0f * db.y;
            }
        }
        float lm = sA[0];
        #pragma unroll
        for (int j = 1; j < 8; j++) lm = fminf(lm, sA[j]);
        #pragma unroll
        for (int j = 0; j < 8; j++) lm = fminf(lm, sB[j]);
        float mn  = funkey(__reduce_min_sync(0xFFFFFFFFu, fkey(lm)));
        float thr = mn + MARGIN;

        uint32_t m16 = 0;
        #pragma unroll
        for (int j = 0; j < 8; j++) {
            m16 |= (sA[j] <= thr) ? (1u << j) : 0u;
            m16 |= (sB[j] <= thr) ? (1u << (8 + j)) : 0u;
        }
        uint32_t ball = __ballot_sync(0xFFFFFFFFu, m16 != 0);
        uint32_t cnt  = __reduce_add_sync(0xFFFFFFFFu, (uint32_t)__popc(m16));

        int besti;
        if (cnt == 1) {
            int src = __ffs(ball) - 1;
            uint32_t m = __shfl_sync(0xFFFFFFFFu, m16, src);
            int b = __ffs(m) - 1;
            besti = (b < 8) ? (8 * src + b) : (256 + 8 * src + (b - 8));
        } else {
            float bestv = 3.4e38f;
            besti = 0x7FFFFFFF;
            uint32_t bl = ball;
            while (bl) {
                int src = __ffs(bl) - 1; bl &= bl - 1;
                uint32_t m = __shfl_sync(0xFFFFFFFFu, m16, src);
                while (m) {
                    int b = __ffs(m) - 1; m &= m - 1;
                    int kc = (b < 8) ? (8 * src + b) : (256 + 8 * src + (b - 8));
                    float4 q = *reinterpret_cast<const float4*>(
                        &emb[(size_t)kc * D_DIM + lane * 4]);
                    float p = zc.x * q.x + zc.y * q.y + zc.z * q.z + zc.w * q.w;
                    #pragma unroll
                    for (int off = 16; off > 0; off >>= 1)
                        p += __shfl_xor_sync(0xFFFFFFFFu, p, off);
                    float s_ex = en[kc] - 2.0f * p;
                    if (s_ex < bestv || (s_ex == bestv && kc < besti)) {
                        bestv = s_ex; besti = kc;
                    }
                }
            }
        }

        if (lane == 0) idxf_out[row] = (float)besti;

        float4 q = *reinterpret_cast<const float4*>(&emb[(size_t)besti * D_DIM + lane * 4]);
        float dx = q.x - zc.x, dy = q.y - zc.y, dz = q.z - zc.z, dw4 = q.w - zc.w;
        float4 st = make_float4(zc.x + dx, zc.y + dy, zc.z + dz, zc.w + dw4);
        *reinterpret_cast<float4*>(&zq_out[(size_t)row * D_DIM + lane * 4]) = st;

        lacc += dx * dx + dy * dy + dz * dz + dw4 * dw4;

        float* dwp = &g_dw[besti * D_DIM + lane * 4];
        asm volatile("red.global.add.v4.f32 [%0], {%1, %2, %3, %4};"
                     :: "l"(dwp), "f"(zc.x), "f"(zc.y), "f"(zc.z), "f"(zc.w)
                     : "memory");
        if (lane == 0) atomicAdd(&g_counts[besti], 1.0f);
    }

    #pragma unroll
    for (int off = 16; off > 0; off >>= 1) lacc += __shfl_xor_sync(0xFFFFFFFFu, lacc, off);
    if (lane == 0) s_l[warp] = lacc;
    __syncthreads();
    if (tid == 0) {
        float b = 0.0f;
        #pragma unroll
        for (int w = 0; w < 8; w++) b += s_l[w];
        atomicAdd(&g_loss_part[blockIdx.x & 63], b);
    }
}

// ============================================================
// Kernel 3a: scalar finalize — ecs EMA, n-reduce, cluster size, loss.
// ============================================================
__global__ void __launch_bounds__(512)
finalize_a(const float* __restrict__ ecs, float* __restrict__ o_ecs,
           float* __restrict__ o_loss, int N) {
    const int k = threadIdx.x;
    __shared__ float red[K_DIM];

    float necs = ecs[k] * DECAY_F + ONE_M_DECAY * g_counts[k];
    o_ecs[k] = necs;
    red[k] = necs;
    __syncthreads();
    #pragma unroll
    for (int s = 256; s > 0; s >>= 1) {
        if (k < s) red[k] += red[k + s];
        __syncthreads();
    }
    float n = red[0];
    g_cs[k] = (necs + EPS_F) / (n + (float)K_DIM * EPS_F) * n;

    if (k == 0) {
        float L = 0.0f;
        #pragma unroll
        for (int j = 0; j < 64; j++) L += g_loss_part[j];
        *o_loss = COMMIT * L / ((float)N * (float)D_DIM);
    }
}

// ============================================================
// Kernel 3b: wide finalize — ema_w EMA + new embedding (K*D elems).
// ============================================================
__global__ void __launch_bounds__(256)
finalize_b(const float* __restrict__ emaw, float* __restrict__ o_emaw,
           float* __restrict__ o_emb) {
    int i = blockIdx.x * 256 + threadIdx.x;
    float w = emaw[i] * DECAY_F + ONE_M_DECAY * g_dw[i];
    o_emaw[i] = w;
    o_emb[i]  = w / g_cs[i >> 7];
}

// ============================================================
// launch
// ============================================================
extern "C" void kernel_launch(void* const* d_in, const int* in_sizes, int n_in,
                              void* d_out, int out_size) {
    const float* z    = (const float*)d_in[0];   // [N, 128]
    const float* emb  = (const float*)d_in[1];   // [512, 128]
    const float* ecs  = (const float*)d_in[2];   // [512]
    const float* emaw = (const float*)d_in[3];   // [512, 128]

    const int ND = in_sizes[0];
    const int KD = in_sizes[1];
    const int K  = in_sizes[2];
    const int N  = ND / D_DIM;

    float* out    = (float*)d_out;
    float* o_zq   = out;                 // N*D
    float* o_loss = o_zq + ND;           // 1
    float* o_idx  = o_loss + 1;          // N
    float* o_ecs  = o_idx + N;           // K
    float* o_emaw = o_ecs + K;           // K*D
    float* o_emb  = o_emaw + KD;         // K*D

    // dyn smem: ebuf 2*64*68 + dots 64*260 (u32) = 101376 B -> 2 CTAs/SM
    const int dyn_smem = (2 * EBUF + 64 * DP) * 4;
    cudaFuncSetAttribute(argmin_kernel,
                         cudaFuncAttributeMaxDynamicSharedMemorySize, dyn_smem);

    init_kernel<<<64, 256>>>(emb);
    argmin_kernel<<<N / 64, 256, dyn_smem>>>(z, emb, o_idx, o_zq);
    finalize_a<<<1, 512>>>(ecs, o_ecs, o_loss, N);
    finalize_b<<<KD / 256, 256>>>(emaw, o_emaw, o_emb);
}